// round 10
// baseline (speedup 1.0000x reference)
#include <cuda_runtime.h>
#include <cuda_bf16.h>
#include <math.h>

// Problem constants (B,T,C) = (8, 4096, 512)
#define Bdim 8
#define Tdim 4096
#define Cdim 512
#define CHUNK 128
#define NCHUNK (Tdim / CHUNK)   // 32

// Scratch (allocation-free rule: __device__ globals)
__device__ __nv_bfloat16 g_yh[Bdim * Tdim * Cdim];   // 32 MB  y hi plane
__device__ __nv_bfloat16 g_yl[Bdim * Tdim * Cdim];   // 32 MB  y lo plane
__device__ __nv_bfloat16 g_wh[Cdim * Cdim];          // 0.5 MB W hi plane
__device__ __nv_bfloat16 g_wl[Cdim * Cdim];          // 0.5 MB W lo plane
__device__ float         g_S[Bdim * NCHUNK * Cdim];  // chunk sums of decay^t * x

// ===========================================================================
// PTX helpers — sm_80+-era instructions ONLY (harness PTX target is sm_103,
// which rejects all tcgen05/TMEM; HMMA via mma.sync is the tensor path).
// ===========================================================================
__device__ __forceinline__ unsigned smem_u32(const void* p) {
    unsigned a;
    asm("{ .reg .u64 t; cvta.to.shared.u64 t, %1; cvt.u32.u64 %0, t; }"
        : "=r"(a) : "l"(p));
    return a;
}

// 16-byte async copy global -> shared (LDGSTS in SASS).
__device__ __forceinline__ void cp16(unsigned smem_dst, const void* gsrc) {
    asm volatile("cp.async.cg.shared.global [%0], [%1], 16;"
                 :: "r"(smem_dst), "l"(gsrc) : "memory");
}
__device__ __forceinline__ void cp_commit() {
    asm volatile("cp.async.commit_group;" ::: "memory");
}
__device__ __forceinline__ void cp_wait1() {
    asm volatile("cp.async.wait_group 1;" ::: "memory");
}
__device__ __forceinline__ void cp_wait0() {
    asm volatile("cp.async.wait_group 0;" ::: "memory");
}

__device__ __forceinline__ void ldm_x4(unsigned* r, unsigned addr) {
    asm volatile("ldmatrix.sync.aligned.m8n8.x4.shared.b16 {%0,%1,%2,%3}, [%4];"
                 : "=r"(r[0]), "=r"(r[1]), "=r"(r[2]), "=r"(r[3]) : "r"(addr));
}

// D += A * B^T  (m16n8k16, bf16 inputs, fp32 accumulate)
__device__ __forceinline__ void mma_bf16(float* d, const unsigned* a,
                                         unsigned b0, unsigned b1) {
    asm volatile(
        "mma.sync.aligned.m16n8k16.row.col.f32.bf16.bf16.f32 "
        "{%0,%1,%2,%3}, {%4,%5,%6,%7}, {%8,%9}, {%0,%1,%2,%3};"
        : "+f"(d[0]), "+f"(d[1]), "+f"(d[2]), "+f"(d[3])
        : "r"(a[0]), "r"(a[1]), "r"(a[2]), "r"(a[3]), "r"(b0), "r"(b1));
}

// ===========================================================================
// W pre-split: mix_w fp32 -> bf16 hi/lo planes (run once; 1 MB total)
// ===========================================================================
__global__ void __launch_bounds__(256) w_split(const float* __restrict__ W)
{
    const int i = blockIdx.x * 256 + threadIdx.x;   // 0 .. Cdim*Cdim-1
    const float v = W[i];
    const __nv_bfloat16 h = __float2bfloat16(v);
    g_wh[i] = h;
    g_wl[i] = __float2bfloat16(v - __bfloat162float(h));
}

// ===========================================================================
// Pass 1: per-chunk sums  S[b,k,c] = sum_{t in chunk k} decay_c^t * x[b,t,c]
// ===========================================================================
__global__ void __launch_bounds__(Cdim) scan_pass1(const float* __restrict__ x,
                                                   const float* __restrict__ log_decay)
{
    const int c  = threadIdx.x;
    const int b  = blockIdx.x / NCHUNK;
    const int k  = blockIdx.x % NCHUNK;
    const int t0 = k * CHUNK;

    const float ld    = log_decay[c];
    const float decay = 1.0f / (1.0f + expf(-ld));   // sigmoid
    const float ld2   = log2f(decay);

    float p = exp2f((float)t0 * ld2);

    const float* xp = x + ((size_t)b * Tdim + t0) * Cdim + c;
    float sum = 0.0f;
#pragma unroll 8
    for (int t = 0; t < CHUNK; ++t) {
        sum = fmaf(p, xp[(size_t)t * Cdim], sum);
        p *= decay;
    }
    g_S[((size_t)b * NCHUNK + k) * Cdim + c] = sum;
}

// ===========================================================================
// Pass 2: y[b,t,c] = decay^{T-1-t} * ( sum_{j<k} S[b,j,c] + local cumsum )
// Stores y split into bf16 hi/lo planes. q refreshed via exp2f every 8 steps.
// ===========================================================================
__global__ void __launch_bounds__(Cdim) scan_pass2(const float* __restrict__ x,
                                                   const float* __restrict__ log_decay)
{
    const int c  = threadIdx.x;
    const int b  = blockIdx.x / NCHUNK;
    const int k  = blockIdx.x % NCHUNK;
    const int t0 = k * CHUNK;

    const float ld    = log_decay[c];
    const float decay = 1.0f / (1.0f + expf(-ld));
    const float ld2   = log2f(decay);
    const float invd  = 1.0f / decay;

    float run = 0.0f;
    for (int j = 0; j < k; ++j)
        run += g_S[((size_t)b * NCHUNK + j) * Cdim + c];

    float p = exp2f((float)t0 * ld2);                 // decay^t
    float q = 0.0f;                                   // decay^{T-1-t}

    const size_t base = ((size_t)b * Tdim + t0) * Cdim + c;
    const float* xp = x + base;
    __nv_bfloat16* yh = g_yh + base;
    __nv_bfloat16* yl = g_yl + base;

#pragma unroll 8
    for (int t = 0; t < CHUNK; ++t) {
        const int g = t0 + t;
        if ((t & 7) == 0)
            q = exp2f((float)(Tdim - 1 - g) * ld2);
        run = fmaf(p, xp[(size_t)t * Cdim], run);
        const float yv = q * run;
        const __nv_bfloat16 h = __float2bfloat16(yv);
        yh[(size_t)t * Cdim] = h;
        yl[(size_t)t * Cdim] = __float2bfloat16(yv - __bfloat162float(h));
        p *= decay;
        q *= invd;
    }
}

// ===========================================================================
// HMMA GEMM (mma.sync): out[m,n] = sum_k y[m,k] * W[n,k] + bias[n]
// M=32768, N=512, K=512. CTA tile 128x128, BK=32, 8 warps (warp tile 32x64),
// double-buffered cp.async smem, 3-term bf16 split (Ah*Bh + Ah*Bl + Al*Bh),
// fp32 register accumulators.
// ===========================================================================
#define GM 128
#define GN 128
#define GK 32
#define NKCHUNK (Cdim / GK)      // 16

// smem: padded rows — 32 halves data + 8 pad = 40 halves = 80 B (conflict-free
// for ldmatrix: row offsets mod 128 are distinct within any 8-row group).
#define ROWB    80
#define PLANE   (128 * ROWB)     // 10240 B
#define BUF     (4 * PLANE)      // 40960 B : planes AH, AL, BH, BL
#define SM_TOTAL (2 * BUF)       // 81920 B

__global__ void __launch_bounds__(256, 1)
mix_gemm_mma(const __nv_bfloat16* __restrict__ Ah,  // [M,K]
             const __nv_bfloat16* __restrict__ Al,  // [M,K]
             const __nv_bfloat16* __restrict__ Wh,  // [N,K]
             const __nv_bfloat16* __restrict__ Wl,  // [N,K]
             const float* __restrict__ bias,        // [N]
             float* __restrict__ out)               // [M,N]
{
    extern __shared__ char smem[];
    const unsigned smem_base = smem_u32(smem);
    const int tid  = threadIdx.x;
    const int wid  = tid >> 5;
    const int lane = tid & 31;

    const int n0 = blockIdx.x * GN;
    const int m0 = blockIdx.y * GM;

    const int warp_m = wid & 3;   // 4 warps along M: 32 rows each
    const int warp_n = wid >> 2;  // 2 warps along N: 64 cols each

    const __nv_bfloat16* srcs[4] = {
        Ah + (size_t)m0 * Cdim,   // plane 0: A hi (128 rows)
        Al + (size_t)m0 * Cdim,   // plane 1: A lo
        Wh + (size_t)n0 * Cdim,   // plane 2: B hi (128 rows)
        Wl + (size_t)n0 * Cdim    // plane 3: B lo
    };

    // Fill one buffer with K-chunk ck: per plane 128 rows x 4 x 16B groups
    // = 512 cp16; 256 threads -> 2 each.
    auto fill = [&](int buf, int ck) {
        const int k0 = ck * GK;
        const unsigned bufb = smem_base + buf * BUF;
#pragma unroll
        for (int pl = 0; pl < 4; ++pl) {
            const unsigned pbase = bufb + pl * PLANE;
#pragma unroll
            for (int i = 0; i < 2; ++i) {
                const int lin = i * 256 + tid;       // 0..511
                const int row = lin >> 2;            // 0..127
                const int gp  = lin & 3;             // 16B group
                cp16(pbase + row * ROWB + gp * 16,
                     srcs[pl] + (size_t)row * Cdim + k0 + gp * 8);
            }
        }
        cp_commit();
    };

    float acc[2][8][4];
#pragma unroll
    for (int mi = 0; mi < 2; ++mi)
#pragma unroll
        for (int nj = 0; nj < 8; ++nj)
#pragma unroll
            for (int e = 0; e < 4; ++e) acc[mi][nj][e] = 0.0f;

    fill(0, 0);

    // Fragment address components (ldmatrix lane pattern).
    const int fr_row = lane & 15;          // row within 16
    const int fr_col = (lane >> 4) * 8;    // 0 or 8 (k offset)

    for (int ck = 0; ck < NKCHUNK; ++ck) {
        const int cur = ck & 1;
        const int nxt = cur ^ 1;

        if (ck + 1 < NKCHUNK) { fill(nxt, ck + 1); cp_wait1(); }
        else                  { cp_wait0(); }
        __syncthreads();   // current buffer visible CTA-wide

        const unsigned bufb = smem_base + cur * BUF;
        const unsigned sAh = bufb + 0 * PLANE;
        const unsigned sAl = bufb + 1 * PLANE;
        const unsigned sBh = bufb + 2 * PLANE;
        const unsigned sBl = bufb + 3 * PLANE;

#pragma unroll
        for (int ks = 0; ks < 2; ++ks) {            // two k16 steps per chunk
            const int kc = ks * 16 + fr_col;

            unsigned ah[2][4], al[2][4], bh[4][4], bl[4][4];
#pragma unroll
            for (int mi = 0; mi < 2; ++mi) {
                const unsigned off = (unsigned)((warp_m * 32 + mi * 16 + fr_row) * ROWB + kc * 2);
                ldm_x4(ah[mi], sAh + off);
                ldm_x4(al[mi], sAl + off);
            }
#pragma unroll
            for (int nq = 0; nq < 4; ++nq) {        // each x4 covers two n8 tiles
                const unsigned off = (unsigned)((warp_n * 64 + nq * 16 + fr_row) * ROWB + kc * 2);
                ldm_x4(bh[nq], sBh + off);
                ldm_x4(bl[nq], sBl + off);
            }

            // Interleave the even/odd accumulator chains: each acc sees its 3
            // dependent MMAs separated by the other chain's issues (and the
            // unrolled mi/nq iterations provide 16 independent chains total).
#pragma unroll
            for (int mi = 0; mi < 2; ++mi)
#pragma unroll
                for (int nq = 0; nq < 4; ++nq) {
                    // tile even: B regs {0,2};  tile odd: B regs {1,3}
                    mma_bf16(acc[mi][nq * 2 + 0], ah[mi], bh[nq][0], bh[nq][2]);
                    mma_bf16(acc[mi][nq * 2 + 1], ah[mi], bh[nq][1], bh[nq][3]);
                    mma_bf16(acc[mi][nq * 2 + 0], ah[mi], bl[nq][0], bl[nq][2]);
                    mma_bf16(acc[mi][nq * 2 + 1], ah[mi], bl[nq][1], bl[nq][3]);
                    mma_bf16(acc[mi][nq * 2 + 0], al[mi], bh[nq][0], bh[nq][2]);
                    mma_bf16(acc[mi][nq * 2 + 1], al[mi], bh[nq][1], bh[nq][3]);
                }
        }
        __syncthreads();   // all reads done before this buffer is refilled
    }

    // ---- epilogue: add bias, store fp32 ----
    // Thread owns C[row=l/4 (+8)][col=2(l%4)+1] per (mi,nj) tile.
    const int erow = lane >> 2;
    const int ecol = (lane & 3) * 2;
#pragma unroll
    for (int mi = 0; mi < 2; ++mi) {
        const int mbase = m0 + warp_m * 32 + mi * 16 + erow;
#pragma unroll
        for (int nj = 0; nj < 8; ++nj) {
            const int col = n0 + warp_n * 64 + nj * 8 + ecol;
            const float b0 = bias[col], b1 = bias[col + 1];
            float2 v0 = make_float2(acc[mi][nj][0] + b0, acc[mi][nj][1] + b1);
            float2 v1 = make_float2(acc[mi][nj][2] + b0, acc[mi][nj][3] + b1);
            *(float2*)(out + (size_t)mbase * Cdim + col)       = v0;
            *(float2*)(out + (size_t)(mbase + 8) * Cdim + col) = v1;
        }
    }
}

// ===========================================================================
// Launch
// ===========================================================================
extern "C" void kernel_launch(void* const* d_in, const int* in_sizes, int n_in,
                              void* d_out, int out_size)
{
    const float* x         = (const float*)d_in[0];  // [B,T,C]
    const float* log_decay = (const float*)d_in[1];  // [C]
    const float* mix_w     = (const float*)d_in[2];  // [C,C]
    const float* mix_b     = (const float*)d_in[3];  // [C]
    float*       out       = (float*)d_out;          // [B,T,C]

    __nv_bfloat16 *yh, *yl, *wh, *wl;
    cudaGetSymbolAddress((void**)&yh, g_yh);
    cudaGetSymbolAddress((void**)&yl, g_yl);
    cudaGetSymbolAddress((void**)&wh, g_wh);
    cudaGetSymbolAddress((void**)&wl, g_wl);

    w_split<<<(Cdim * Cdim) / 256, 256>>>(mix_w);
    scan_pass1<<<Bdim * NCHUNK, Cdim>>>(x, log_decay);
    scan_pass2<<<Bdim * NCHUNK, Cdim>>>(x, log_decay);

    cudaFuncSetAttribute(mix_gemm_mma, cudaFuncAttributeMaxDynamicSharedMemorySize, SM_TOTAL);
    dim3 grid(Cdim / GN, (Bdim * Tdim) / GM);   // (4, 256)
    mix_gemm_mma<<<grid, 256, SM_TOTAL>>>(yh, yl, wh, wl, mix_b, out);
}

// round 17
// speedup vs baseline: 1.0976x; 1.0976x over previous
#include <cuda_runtime.h>
#include <cuda_bf16.h>
#include <math.h>

// Problem constants (B,T,C) = (8, 4096, 512)
#define Bdim 8
#define Tdim 4096
#define Cdim 512
#define CHUNK 128
#define NCHUNK (Tdim / CHUNK)   // 32

// Scratch (allocation-free rule: __device__ globals)
__device__ __nv_bfloat16 g_yh[Bdim * Tdim * Cdim];   // 32 MB  y hi plane
__device__ __nv_bfloat16 g_yl[Bdim * Tdim * Cdim];   // 32 MB  y lo plane
__device__ __nv_bfloat16 g_wh[Cdim * Cdim];          // 0.5 MB W hi plane
__device__ __nv_bfloat16 g_wl[Cdim * Cdim];          // 0.5 MB W lo plane
__device__ float         g_S[Bdim * NCHUNK * Cdim];  // chunk sums of decay^t * x

// ===========================================================================
// PTX helpers — sm_80+-era instructions ONLY (harness PTX target sm_103).
// ===========================================================================
__device__ __forceinline__ unsigned smem_u32(const void* p) {
    unsigned a;
    asm("{ .reg .u64 t; cvta.to.shared.u64 t, %1; cvt.u32.u64 %0, t; }"
        : "=r"(a) : "l"(p));
    return a;
}

// 16-byte async copy global -> shared (LDGSTS in SASS).
__device__ __forceinline__ void cp16(unsigned smem_dst, const void* gsrc) {
    asm volatile("cp.async.cg.shared.global [%0], [%1], 16;"
                 :: "r"(smem_dst), "l"(gsrc) : "memory");
}
__device__ __forceinline__ void cp_commit() {
    asm volatile("cp.async.commit_group;" ::: "memory");
}
__device__ __forceinline__ void cp_wait1() {
    asm volatile("cp.async.wait_group 1;" ::: "memory");
}
__device__ __forceinline__ void cp_wait0() {
    asm volatile("cp.async.wait_group 0;" ::: "memory");
}

__device__ __forceinline__ void ldm_x4(unsigned* r, unsigned addr) {
    asm volatile("ldmatrix.sync.aligned.m8n8.x4.shared.b16 {%0,%1,%2,%3}, [%4];"
                 : "=r"(r[0]), "=r"(r[1]), "=r"(r[2]), "=r"(r[3]) : "r"(addr));
}

// D += A * B^T  (m16n8k16, bf16 inputs, fp32 accumulate)
__device__ __forceinline__ void mma_bf16(float* d, const unsigned* a,
                                         unsigned b0, unsigned b1) {
    asm volatile(
        "mma.sync.aligned.m16n8k16.row.col.f32.bf16.bf16.f32 "
        "{%0,%1,%2,%3}, {%4,%5,%6,%7}, {%8,%9}, {%0,%1,%2,%3};"
        : "+f"(d[0]), "+f"(d[1]), "+f"(d[2]), "+f"(d[3])
        : "r"(a[0]), "r"(a[1]), "r"(a[2]), "r"(a[3]), "r"(b0), "r"(b1));
}

// ===========================================================================
// W pre-split: mix_w fp32 -> bf16 hi/lo planes (run once; 1 MB total)
// ===========================================================================
__global__ void __launch_bounds__(256) w_split(const float* __restrict__ W)
{
    const int i = blockIdx.x * 256 + threadIdx.x;   // 0 .. Cdim*Cdim-1
    const float v = W[i];
    const __nv_bfloat16 h = __float2bfloat16(v);
    g_wh[i] = h;
    g_wl[i] = __float2bfloat16(v - __bfloat162float(h));
}

// ===========================================================================
// Pass 1: per-chunk sums  S[b,k,c] = sum_{t in chunk k} decay_c^t * x[b,t,c]
// ===========================================================================
__global__ void __launch_bounds__(Cdim) scan_pass1(const float* __restrict__ x,
                                                   const float* __restrict__ log_decay)
{
    const int c  = threadIdx.x;
    const int b  = blockIdx.x / NCHUNK;
    const int k  = blockIdx.x % NCHUNK;
    const int t0 = k * CHUNK;

    const float ld    = log_decay[c];
    const float decay = 1.0f / (1.0f + expf(-ld));   // sigmoid
    const float ld2   = log2f(decay);

    float p = exp2f((float)t0 * ld2);

    const float* xp = x + ((size_t)b * Tdim + t0) * Cdim + c;
    float sum = 0.0f;
#pragma unroll 8
    for (int t = 0; t < CHUNK; ++t) {
        sum = fmaf(p, xp[(size_t)t * Cdim], sum);
        p *= decay;
    }
    g_S[((size_t)b * NCHUNK + k) * Cdim + c] = sum;
}

// ===========================================================================
// Pass 2: y[b,t,c] = decay^{T-1-t} * ( sum_{j<k} S[b,j,c] + local cumsum )
// Stores y split into bf16 hi/lo planes. q refreshed via exp2f every 8 steps.
// ===========================================================================
__global__ void __launch_bounds__(Cdim) scan_pass2(const float* __restrict__ x,
                                                   const float* __restrict__ log_decay)
{
    const int c  = threadIdx.x;
    const int b  = blockIdx.x / NCHUNK;
    const int k  = blockIdx.x % NCHUNK;
    const int t0 = k * CHUNK;

    const float ld    = log_decay[c];
    const float decay = 1.0f / (1.0f + expf(-ld));
    const float ld2   = log2f(decay);
    const float invd  = 1.0f / decay;

    float run = 0.0f;
    for (int j = 0; j < k; ++j)
        run += g_S[((size_t)b * NCHUNK + j) * Cdim + c];

    float p = exp2f((float)t0 * ld2);                 // decay^t
    float q = 0.0f;                                   // decay^{T-1-t}

    const size_t base = ((size_t)b * Tdim + t0) * Cdim + c;
    const float* xp = x + base;
    __nv_bfloat16* yh = g_yh + base;
    __nv_bfloat16* yl = g_yl + base;

#pragma unroll 8
    for (int t = 0; t < CHUNK; ++t) {
        const int g = t0 + t;
        if ((t & 7) == 0)
            q = exp2f((float)(Tdim - 1 - g) * ld2);
        run = fmaf(p, xp[(size_t)t * Cdim], run);
        const float yv = q * run;
        const __nv_bfloat16 h = __float2bfloat16(yv);
        yh[(size_t)t * Cdim] = h;
        yl[(size_t)t * Cdim] = __float2bfloat16(yv - __bfloat162float(h));
        p *= decay;
        q *= invd;
    }
}

// ===========================================================================
// HMMA GEMM (mma.sync): out[m,n] = sum_k y[m,k] * W[n,k] + bias[n]
// M=32768, N=512, K=512. CTA tile 128x128, BK=32, 8 warps (warp tile 32x64),
// double-buffered cp.async smem, 3-term bf16 split (Ah*Bh + Ah*Bl + Al*Bh),
// fp32 register accumulators.  Target 2 CTAs/SM (regs capped at 128;
// B fragments loaded per-nq to keep live registers ~110).
// ===========================================================================
#define GM 128
#define GN 128
#define GK 32
#define NKCHUNK (Cdim / GK)      // 16

// smem: padded rows — 32 halves data + 8 pad = 40 halves = 80 B (conflict-free
// for ldmatrix: row offsets mod 128 are distinct within any 8-row group).
#define ROWB    80
#define PLANE   (128 * ROWB)     // 10240 B
#define BUF     (4 * PLANE)      // 40960 B : planes AH, AL, BH, BL
#define SM_TOTAL (2 * BUF)       // 81920 B  (2 CTAs x 80KB = 160KB <= 227KB)

__global__ void __launch_bounds__(256, 2)
mix_gemm_mma(const __nv_bfloat16* __restrict__ Ah,  // [M,K]
             const __nv_bfloat16* __restrict__ Al,  // [M,K]
             const __nv_bfloat16* __restrict__ Wh,  // [N,K]
             const __nv_bfloat16* __restrict__ Wl,  // [N,K]
             const float* __restrict__ bias,        // [N]
             float* __restrict__ out)               // [M,N]
{
    extern __shared__ char smem[];
    const unsigned smem_base = smem_u32(smem);
    const int tid  = threadIdx.x;
    const int wid  = tid >> 5;
    const int lane = tid & 31;

    const int n0 = blockIdx.x * GN;
    const int m0 = blockIdx.y * GM;

    const int warp_m = wid & 3;   // 4 warps along M: 32 rows each
    const int warp_n = wid >> 2;  // 2 warps along N: 64 cols each

    const __nv_bfloat16* srcs[4] = {
        Ah + (size_t)m0 * Cdim,   // plane 0: A hi (128 rows)
        Al + (size_t)m0 * Cdim,   // plane 1: A lo
        Wh + (size_t)n0 * Cdim,   // plane 2: B hi (128 rows)
        Wl + (size_t)n0 * Cdim    // plane 3: B lo
    };

    // Fill one buffer with K-chunk ck: per plane 128 rows x 4 x 16B groups
    // = 512 cp16; 256 threads -> 2 each.
    auto fill = [&](int buf, int ck) {
        const int k0 = ck * GK;
        const unsigned bufb = smem_base + buf * BUF;
#pragma unroll
        for (int pl = 0; pl < 4; ++pl) {
            const unsigned pbase = bufb + pl * PLANE;
#pragma unroll
            for (int i = 0; i < 2; ++i) {
                const int lin = i * 256 + tid;       // 0..511
                const int row = lin >> 2;            // 0..127
                const int gp  = lin & 3;             // 16B group
                cp16(pbase + row * ROWB + gp * 16,
                     srcs[pl] + (size_t)row * Cdim + k0 + gp * 8);
            }
        }
        cp_commit();
    };

    float acc[2][8][4];
#pragma unroll
    for (int mi = 0; mi < 2; ++mi)
#pragma unroll
        for (int nj = 0; nj < 8; ++nj)
#pragma unroll
            for (int e = 0; e < 4; ++e) acc[mi][nj][e] = 0.0f;

    fill(0, 0);

    // Fragment address components (ldmatrix lane pattern).
    const int fr_row = lane & 15;          // row within 16
    const int fr_col = (lane >> 4) * 8;    // 0 or 8 (k offset)

    for (int ck = 0; ck < NKCHUNK; ++ck) {
        const int cur = ck & 1;
        const int nxt = cur ^ 1;

        if (ck + 1 < NKCHUNK) { fill(nxt, ck + 1); cp_wait1(); }
        else                  { cp_wait0(); }
        __syncthreads();   // current buffer visible CTA-wide

        const unsigned bufb = smem_base + cur * BUF;
        const unsigned sAh = bufb + 0 * PLANE;
        const unsigned sAl = bufb + 1 * PLANE;
        const unsigned sBh = bufb + 2 * PLANE;
        const unsigned sBl = bufb + 3 * PLANE;

#pragma unroll
        for (int ks = 0; ks < 2; ++ks) {            // two k16 steps per chunk
            const int kc = ks * 16 + fr_col;

            // A fragments for both m16 tiles (live across the nq loop).
            unsigned ah[2][4], al[2][4];
#pragma unroll
            for (int mi = 0; mi < 2; ++mi) {
                const unsigned off = (unsigned)((warp_m * 32 + mi * 16 + fr_row) * ROWB + kc * 2);
                ldm_x4(ah[mi], sAh + off);
                ldm_x4(al[mi], sAl + off);
            }

            // B fragments loaded per-nq (keeps live regs low for 2 CTAs/SM).
#pragma unroll
            for (int nq = 0; nq < 4; ++nq) {        // each x4 covers two n8 tiles
                unsigned bh[4], bl[4];
                const unsigned off = (unsigned)((warp_n * 64 + nq * 16 + fr_row) * ROWB + kc * 2);
                ldm_x4(bh, sBh + off);
                ldm_x4(bl, sBl + off);

                // Interleave even/odd accumulator chains across mi for ILP.
#pragma unroll
                for (int mi = 0; mi < 2; ++mi) {
                    mma_bf16(acc[mi][nq * 2 + 0], ah[mi], bh[0], bh[2]);
                    mma_bf16(acc[mi][nq * 2 + 1], ah[mi], bh[1], bh[3]);
                    mma_bf16(acc[mi][nq * 2 + 0], ah[mi], bl[0], bl[2]);
                    mma_bf16(acc[mi][nq * 2 + 1], ah[mi], bl[1], bl[3]);
                    mma_bf16(acc[mi][nq * 2 + 0], al[mi], bh[0], bh[2]);
                    mma_bf16(acc[mi][nq * 2 + 1], al[mi], bh[1], bh[3]);
                }
            }
        }
        __syncthreads();   // all reads done before this buffer is refilled
    }

    // ---- epilogue: add bias, store fp32 ----
    // Thread owns C[row=l/4 (+8)][col=2(l%4)+1] per (mi,nj) tile.
    const int erow = lane >> 2;
    const int ecol = (lane & 3) * 2;
#pragma unroll
    for (int mi = 0; mi < 2; ++mi) {
        const int mbase = m0 + warp_m * 32 + mi * 16 + erow;
#pragma unroll
        for (int nj = 0; nj < 8; ++nj) {
            const int col = n0 + warp_n * 64 + nj * 8 + ecol;
            const float b0 = bias[col], b1 = bias[col + 1];
            float2 v0 = make_float2(acc[mi][nj][0] + b0, acc[mi][nj][1] + b1);
            float2 v1 = make_float2(acc[mi][nj][2] + b0, acc[mi][nj][3] + b1);
            *(float2*)(out + (size_t)mbase * Cdim + col)       = v0;
            *(float2*)(out + (size_t)(mbase + 8) * Cdim + col) = v1;
        }
    }
}

// ===========================================================================
// Launch
// ===========================================================================
extern "C" void kernel_launch(void* const* d_in, const int* in_sizes, int n_in,
                              void* d_out, int out_size)
{
    const float* x         = (const float*)d_in[0];  // [B,T,C]
    const float* log_decay = (const float*)d_in[1];  // [C]
    const float* mix_w     = (const float*)d_in[2];  // [C,C]
    const float* mix_b     = (const float*)d_in[3];  // [C]
    float*       out       = (float*)d_out;          // [B,T,C]

    __nv_bfloat16 *yh, *yl, *wh, *wl;
    cudaGetSymbolAddress((void**)&yh, g_yh);
    cudaGetSymbolAddress((void**)&yl, g_yl);
    cudaGetSymbolAddress((void**)&wh, g_wh);
    cudaGetSymbolAddress((void**)&wl, g_wl);

    w_split<<<(Cdim * Cdim) / 256, 256>>>(mix_w);
    scan_pass1<<<Bdim * NCHUNK, Cdim>>>(x, log_decay);
    scan_pass2<<<Bdim * NCHUNK, Cdim>>>(x, log_decay);

    cudaFuncSetAttribute(mix_gemm_mma, cudaFuncAttributeMaxDynamicSharedMemorySize, SM_TOTAL);
    dim3 grid(Cdim / GN, (Bdim * Tdim) / GM);   // (4, 256)
    mix_gemm_mma<<<grid, 256, SM_TOTAL>>>(yh, yl, wh, wl, mix_b, out);
}